// round 1
// baseline (speedup 1.0000x reference)
#include <cuda_runtime.h>
#include <math.h>

// Problem constants
#define CCH   512
#define TT    8
#define HWN   4096                  // h*w
#define PN    (TT*HWN)              // 32768 positions
#define GROUPS 32
#define CPG   16
#define GSIZE (CPG*PN)              // 524288 elems per group (contiguous in x)

// ---------------- scratch (device globals; no allocation allowed) ----------
__device__ float g_mean[GROUPS];
__device__ float g_rstd[GROUPS];
__device__ float g_hl[(size_t)PN * CCH];   // channels-last normalized input / reused for proj out
__device__ float g_q [(size_t)PN * CCH];
__device__ float g_k [(size_t)PN * CCH];
__device__ float g_v [(size_t)PN * CCH];
__device__ float g_o [(size_t)PN * CCH];
__device__ float g_S [(size_t)HWN * HWN];  // 4096x4096 scores, reused per bt slice

// ---------------- group-norm statistics ------------------------------------
__global__ void __launch_bounds__(512) gn_stats(const float* __restrict__ x) {
    int g = blockIdx.x;
    const float4* p = (const float4*)(x + (size_t)g * GSIZE);
    float s = 0.f, ss = 0.f;
    for (int i = threadIdx.x; i < GSIZE / 4; i += 512) {
        float4 v = p[i];
        s  += v.x + v.y + v.z + v.w;
        ss += v.x * v.x + v.y * v.y + v.z * v.z + v.w * v.w;
    }
    __shared__ float shs[512];
    __shared__ float shq[512];
    shs[threadIdx.x] = s; shq[threadIdx.x] = ss;
    __syncthreads();
    for (int st = 256; st > 0; st >>= 1) {
        if (threadIdx.x < st) {
            shs[threadIdx.x] += shs[threadIdx.x + st];
            shq[threadIdx.x] += shq[threadIdx.x + st];
        }
        __syncthreads();
    }
    if (threadIdx.x == 0) {
        float m = shs[0] / (float)GSIZE;
        float var = shq[0] / (float)GSIZE - m * m;
        g_mean[g] = m;
        g_rstd[g] = rsqrtf(var + 1e-6f);
    }
}

// ---------------- normalize + transpose to channels-last --------------------
// x: [C][P] (stride 32768), hl: [P][C]
__global__ void __launch_bounds__(1024) norm_transpose(
    const float* __restrict__ x, const float* __restrict__ gamma,
    const float* __restrict__ beta, float* __restrict__ hl)
{
    __shared__ float tile[32][33];
    int p0 = blockIdx.x * 32, c0 = blockIdx.y * 32;
    int c = c0 + threadIdx.y;
    tile[threadIdx.y][threadIdx.x] = x[(size_t)c * PN + p0 + threadIdx.x];
    __syncthreads();
    int cc = c0 + threadIdx.x;
    int g = cc >> 4;
    float a = gamma[cc] * g_rstd[g];
    float b = beta[cc] - g_mean[g] * a;
    hl[(size_t)(p0 + threadIdx.y) * CCH + cc] = tile[threadIdx.x][threadIdx.y] * a + b;
}

// ---------------- residual add + transpose back to channels-first ----------
__global__ void __launch_bounds__(1024) add_transpose(
    const float* __restrict__ x, const float* __restrict__ ol, float* __restrict__ out)
{
    __shared__ float tile[32][33];
    int p0 = blockIdx.x * 32, c0 = blockIdx.y * 32;
    tile[threadIdx.y][threadIdx.x] = ol[(size_t)(p0 + threadIdx.y) * CCH + c0 + threadIdx.x];
    __syncthreads();
    size_t idx = (size_t)(c0 + threadIdx.y) * PN + p0 + threadIdx.x;
    out[idx] = x[idx] + tile[threadIdx.x][threadIdx.y];
}

// ---------------- tiled SGEMM: C = scale * (A @ B[^T]) [+ bias] -------------
// 128x128 block tile, K-tile 8, 256 threads, 8x8 per thread (4+4 split layout)
template<bool BT, bool BIAS>
__global__ void __launch_bounds__(256) gemm128(
    const float* __restrict__ A, const float* __restrict__ B,
    const float* __restrict__ bias, float* __restrict__ Cmat,
    int M, int N, int K, float scale)
{
    __shared__ float As[8][128];
    __shared__ float Bs[8][128];
    const int bm0 = blockIdx.y * 128;
    const int bn0 = blockIdx.x * 128;
    const int tid = threadIdx.x;
    const int tx = tid & 15;
    const int ty = tid >> 4;

    float acc[8][8];
    #pragma unroll
    for (int i = 0; i < 8; ++i)
        #pragma unroll
        for (int j = 0; j < 8; ++j) acc[i][j] = 0.f;

    const int lrow = tid >> 1;         // 0..127
    const int lk   = (tid & 1) * 4;    // 0 or 4
    const int bk   = tid >> 5;         // 0..7 (NN B load)
    const int bcol = (tid & 31) * 4;

    for (int k0 = 0; k0 < K; k0 += 8) {
        float4 a = *(const float4*)(A + (size_t)(bm0 + lrow) * K + k0 + lk);
        As[lk + 0][lrow] = a.x; As[lk + 1][lrow] = a.y;
        As[lk + 2][lrow] = a.z; As[lk + 3][lrow] = a.w;
        if (BT) {
            float4 b = *(const float4*)(B + (size_t)(bn0 + lrow) * K + k0 + lk);
            Bs[lk + 0][lrow] = b.x; Bs[lk + 1][lrow] = b.y;
            Bs[lk + 2][lrow] = b.z; Bs[lk + 3][lrow] = b.w;
        } else {
            float4 b = *(const float4*)(B + (size_t)(k0 + bk) * N + bn0 + bcol);
            *(float4*)&Bs[bk][bcol] = b;
        }
        __syncthreads();
        #pragma unroll
        for (int kk = 0; kk < 8; ++kk) {
            float ra[8], rb[8];
            *(float4*)(ra)     = *(const float4*)&As[kk][ty * 4];
            *(float4*)(ra + 4) = *(const float4*)&As[kk][64 + ty * 4];
            *(float4*)(rb)     = *(const float4*)&Bs[kk][tx * 4];
            *(float4*)(rb + 4) = *(const float4*)&Bs[kk][64 + tx * 4];
            #pragma unroll
            for (int i = 0; i < 8; ++i)
                #pragma unroll
                for (int j = 0; j < 8; ++j)
                    acc[i][j] = fmaf(ra[i], rb[j], acc[i][j]);
        }
        __syncthreads();
    }

    #pragma unroll
    for (int ih = 0; ih < 2; ++ih) {
        #pragma unroll
        for (int i = 0; i < 4; ++i) {
            int r = bm0 + ih * 64 + ty * 4 + i;
            #pragma unroll
            for (int jh = 0; jh < 2; ++jh) {
                int cb = bn0 + jh * 64 + tx * 4;
                float* ac = &acc[ih * 4 + i][jh * 4];
                float4 o;
                o.x = ac[0] * scale; o.y = ac[1] * scale;
                o.z = ac[2] * scale; o.w = ac[3] * scale;
                if (BIAS) {
                    o.x += bias[cb + 0]; o.y += bias[cb + 1];
                    o.z += bias[cb + 2]; o.w += bias[cb + 3];
                }
                *(float4*)(Cmat + (size_t)r * N + cb) = o;
            }
        }
    }
}

// ---------------- row softmax over 4096-wide rows ---------------------------
__global__ void __launch_bounds__(256) softmax4096(float* __restrict__ S) {
    __shared__ float redm[8];
    __shared__ float reds[8];
    float4* p = (float4*)(S + (size_t)blockIdx.x * HWN);
    float4 v[4];
    #pragma unroll
    for (int i = 0; i < 4; ++i) v[i] = p[threadIdx.x + 256 * i];

    float m = -3.4e38f;
    #pragma unroll
    for (int i = 0; i < 4; ++i) {
        m = fmaxf(m, fmaxf(fmaxf(v[i].x, v[i].y), fmaxf(v[i].z, v[i].w)));
    }
    #pragma unroll
    for (int o = 16; o > 0; o >>= 1) m = fmaxf(m, __shfl_xor_sync(0xffffffffu, m, o));
    int wid = threadIdx.x >> 5, lane = threadIdx.x & 31;
    if (lane == 0) redm[wid] = m;
    __syncthreads();
    if (wid == 0) {
        float t = (lane < 8) ? redm[lane] : -3.4e38f;
        #pragma unroll
        for (int o = 16; o > 0; o >>= 1) t = fmaxf(t, __shfl_xor_sync(0xffffffffu, t, o));
        if (lane == 0) redm[0] = t;
    }
    __syncthreads();
    m = redm[0];

    float s = 0.f;
    #pragma unroll
    for (int i = 0; i < 4; ++i) {
        v[i].x = __expf(v[i].x - m); v[i].y = __expf(v[i].y - m);
        v[i].z = __expf(v[i].z - m); v[i].w = __expf(v[i].w - m);
        s += v[i].x + v[i].y + v[i].z + v[i].w;
    }
    #pragma unroll
    for (int o = 16; o > 0; o >>= 1) s += __shfl_xor_sync(0xffffffffu, s, o);
    if (lane == 0) reds[wid] = s;
    __syncthreads();
    if (wid == 0) {
        float t = (lane < 8) ? reds[lane] : 0.f;
        #pragma unroll
        for (int o = 16; o > 0; o >>= 1) t += __shfl_xor_sync(0xffffffffu, t, o);
        if (lane == 0) reds[0] = t;
    }
    __syncthreads();
    float inv = 1.f / reds[0];
    #pragma unroll
    for (int i = 0; i < 4; ++i) {
        v[i].x *= inv; v[i].y *= inv; v[i].z *= inv; v[i].w *= inv;
        p[threadIdx.x + 256 * i] = v[i];
    }
}

// ---------------- launch -----------------------------------------------------
extern "C" void kernel_launch(void* const* d_in, const int* in_sizes, int n_in,
                              void* d_out, int out_size)
{
    const float* x     = (const float*)d_in[0];
    const float* gamma = (const float*)d_in[1];
    const float* beta  = (const float*)d_in[2];
    const float* wq    = (const float*)d_in[3];
    const float* bq    = (const float*)d_in[4];
    const float* wk    = (const float*)d_in[5];
    const float* bk    = (const float*)d_in[6];
    const float* wv    = (const float*)d_in[7];
    const float* bv    = (const float*)d_in[8];
    const float* wp    = (const float*)d_in[9];
    const float* bp    = (const float*)d_in[10];
    float* out = (float*)d_out;

    float *hl, *q, *k, *v, *o, *S;
    cudaGetSymbolAddress((void**)&hl, g_hl);
    cudaGetSymbolAddress((void**)&q,  g_q);
    cudaGetSymbolAddress((void**)&k,  g_k);
    cudaGetSymbolAddress((void**)&v,  g_v);
    cudaGetSymbolAddress((void**)&o,  g_o);
    cudaGetSymbolAddress((void**)&S,  g_S);

    dim3 tb(32, 32);

    gn_stats<<<GROUPS, 512>>>(x);
    norm_transpose<<<dim3(PN / 32, CCH / 32), tb>>>(x, gamma, beta, hl);

    gemm128<false, true><<<dim3(CCH / 128, PN / 128), 256>>>(hl, wq, bq, q, PN, CCH, CCH, 1.f);
    gemm128<false, true><<<dim3(CCH / 128, PN / 128), 256>>>(hl, wk, bk, k, PN, CCH, CCH, 1.f);
    gemm128<false, true><<<dim3(CCH / 128, PN / 128), 256>>>(hl, wv, bv, v, PN, CCH, CCH, 1.f);

    const float scale = 0.044194173824159216f;  // 512^-0.5
    for (int t = 0; t < TT; ++t) {
        const float* qb = q + (size_t)t * HWN * CCH;
        const float* kb = k + (size_t)t * HWN * CCH;
        const float* vb = v + (size_t)t * HWN * CCH;
        float*       ob = o + (size_t)t * HWN * CCH;
        gemm128<true, false><<<dim3(HWN / 128, HWN / 128), 256>>>(qb, kb, nullptr, S, HWN, HWN, CCH, scale);
        softmax4096<<<HWN, 256>>>(S);
        gemm128<false, false><<<dim3(CCH / 128, HWN / 128), 256>>>(S, vb, nullptr, ob, HWN, CCH, HWN, 1.f);
    }

    gemm128<false, true><<<dim3(CCH / 128, PN / 128), 256>>>(o, wp, bp, hl, PN, CCH, CCH, 1.f);
    add_transpose<<<dim3(PN / 32, CCH / 32), tb>>>(x, hl, out);
}

// round 3
// speedup vs baseline: 6.7438x; 6.7438x over previous
#include <cuda_runtime.h>
#include <cuda_bf16.h>
#include <math.h>
#include <stdint.h>

#define CCH   512
#define TT    8
#define HWN   4096
#define PN    (TT*HWN)
#define GROUPS 32
#define GSIZE (16*PN)

// ---------------- scratch (device globals) ----------------------------------
__device__ float g_mean[GROUPS];
__device__ float g_rstd[GROUPS];
__device__ __nv_bfloat16 g_hl[(size_t)PN * CCH];
__device__ __nv_bfloat16 g_q [(size_t)PN * CCH];
__device__ __nv_bfloat16 g_k [(size_t)PN * CCH];
__device__ __nv_bfloat16 g_v [(size_t)PN * CCH];
__device__ __nv_bfloat16 g_vt[(size_t)PN * CCH];
__device__ __nv_bfloat16 g_o [(size_t)PN * CCH];
__device__ float         g_po[(size_t)PN * CCH];
__device__ float         g_S [(size_t)TT * HWN * HWN];   // 512 MB
__device__ __nv_bfloat16 g_P [(size_t)TT * HWN * HWN];   // 256 MB
__device__ __nv_bfloat16 g_wt[4 * CCH * CCH];

// ---------------- PTX helpers -------------------------------------------------
__device__ __forceinline__ uint32_t smem_u32(const void* p) {
    uint32_t a;
    asm("{ .reg .u64 t; cvta.to.shared.u64 t, %1; cvt.u32.u64 %0, t; }" : "=r"(a) : "l"(p));
    return a;
}
__device__ __forceinline__ void ldsm_x4(uint32_t& r0, uint32_t& r1, uint32_t& r2,
                                        uint32_t& r3, uint32_t addr) {
    asm volatile("ldmatrix.sync.aligned.m8n8.x4.shared.b16 {%0,%1,%2,%3}, [%4];"
                 : "=r"(r0), "=r"(r1), "=r"(r2), "=r"(r3) : "r"(addr));
}
__device__ __forceinline__ void mma16816(float* d, const uint32_t* a, const uint32_t* b) {
    asm volatile("mma.sync.aligned.m16n8k16.row.col.f32.bf16.bf16.f32 "
                 "{%0,%1,%2,%3}, {%4,%5,%6,%7}, {%8,%9}, {%0,%1,%2,%3};"
                 : "+f"(d[0]), "+f"(d[1]), "+f"(d[2]), "+f"(d[3])
                 : "r"(a[0]), "r"(a[1]), "r"(a[2]), "r"(a[3]), "r"(b[0]), "r"(b[1]));
}
__device__ __forceinline__ void cp16(uint32_t sm, const void* gp) {
    asm volatile("cp.async.cg.shared.global [%0], [%1], 16;" :: "r"(sm), "l"(gp) : "memory");
}
#define CP_COMMIT() asm volatile("cp.async.commit_group;" ::: "memory")
template<int W> __device__ __forceinline__ void cp_wait() {
    asm volatile("cp.async.wait_group %0;" :: "n"(W) : "memory");
}

// ---------------- group-norm stats --------------------------------------------
__global__ void __launch_bounds__(512) gn_stats(const float* __restrict__ x) {
    int g = blockIdx.x;
    const float4* p = (const float4*)(x + (size_t)g * GSIZE);
    float s = 0.f, ss = 0.f;
    for (int i = threadIdx.x; i < GSIZE / 4; i += 512) {
        float4 v = p[i];
        s  += v.x + v.y + v.z + v.w;
        ss += v.x * v.x + v.y * v.y + v.z * v.z + v.w * v.w;
    }
    __shared__ float shs[512], shq[512];
    shs[threadIdx.x] = s; shq[threadIdx.x] = ss;
    __syncthreads();
    for (int st = 256; st > 0; st >>= 1) {
        if (threadIdx.x < st) {
            shs[threadIdx.x] += shs[threadIdx.x + st];
            shq[threadIdx.x] += shq[threadIdx.x + st];
        }
        __syncthreads();
    }
    if (threadIdx.x == 0) {
        float m = shs[0] / (float)GSIZE;
        float var = shq[0] / (float)GSIZE - m * m;
        g_mean[g] = m;
        g_rstd[g] = rsqrtf(var + 1e-6f);
    }
}

// ---------------- normalize + transpose to channels-last (bf16) ---------------
__global__ void __launch_bounds__(1024) norm_transpose(
    const float* __restrict__ x, const float* __restrict__ gamma,
    const float* __restrict__ beta, __nv_bfloat16* __restrict__ hl)
{
    __shared__ float tile[32][33];
    int p0 = blockIdx.x * 32, c0 = blockIdx.y * 32;
    int c = c0 + threadIdx.y;
    tile[threadIdx.y][threadIdx.x] = x[(size_t)c * PN + p0 + threadIdx.x];
    __syncthreads();
    int cc = c0 + threadIdx.x;
    int g = cc >> 4;
    float a = gamma[cc] * g_rstd[g];
    float b = beta[cc] - g_mean[g] * a;
    hl[(size_t)(p0 + threadIdx.y) * CCH + cc] =
        __float2bfloat16(tile[threadIdx.x][threadIdx.y] * a + b);
}

// ---------------- weight transpose fp32 [K][N] -> bf16 [N][K] ------------------
__global__ void __launch_bounds__(1024) wtrans(const float* __restrict__ W,
                                               __nv_bfloat16* __restrict__ Wt)
{
    __shared__ float t[32][33];
    int k0 = blockIdx.y * 32, n0 = blockIdx.x * 32;
    t[threadIdx.y][threadIdx.x] = W[(size_t)(k0 + threadIdx.y) * CCH + n0 + threadIdx.x];
    __syncthreads();
    Wt[(size_t)(n0 + threadIdx.y) * CCH + k0 + threadIdx.x] =
        __float2bfloat16(t[threadIdx.x][threadIdx.y]);
}

// ---------------- V transpose bf16 [t*4096+p][c] -> [t][c][p] -------------------
__global__ void __launch_bounds__(1024) vtrans(const __nv_bfloat16* __restrict__ v,
                                               __nv_bfloat16* __restrict__ vt)
{
    __shared__ __nv_bfloat16 t[32][33];
    int ts = blockIdx.z, p0 = blockIdx.x * 32, c0 = blockIdx.y * 32;
    t[threadIdx.y][threadIdx.x] =
        v[(size_t)(ts * HWN + p0 + threadIdx.y) * CCH + c0 + threadIdx.x];
    __syncthreads();
    vt[(size_t)ts * CCH * HWN + (size_t)(c0 + threadIdx.y) * HWN + p0 + threadIdx.x] =
        t[threadIdx.x][threadIdx.y];
}

// ---------------- residual add + transpose back --------------------------------
__global__ void __launch_bounds__(1024) add_transpose(
    const float* __restrict__ x, const float* __restrict__ ol, float* __restrict__ out)
{
    __shared__ float tile[32][33];
    int p0 = blockIdx.x * 32, c0 = blockIdx.y * 32;
    tile[threadIdx.y][threadIdx.x] = ol[(size_t)(p0 + threadIdx.y) * CCH + c0 + threadIdx.x];
    __syncthreads();
    size_t idx = (size_t)(c0 + threadIdx.y) * PN + p0 + threadIdx.x;
    out[idx] = x[idx] + tile[threadIdx.x][threadIdx.y];
}

// ---------------- HMMA bf16 GEMM: C = scale*(A @ B^T) [+ bias] ------------------
// A: [M][K] bf16 row-major, B: [N][K] bf16 row-major.
// CTA tile 128x128x32, 8 warps (4x2), warp tile 32x64, 3-stage cp.async pipeline.
#define BM 128
#define BN 128
#define BK 32
#define PADK 40                     // padded row stride in elems (80 B): 5*16B -> 8 bank groups
#define STAGE_ELEMS (BM * PADK)
#define SMEM_GEMM (3 * 2 * STAGE_ELEMS * 2)   // 61440 B

__device__ __forceinline__ void load_tile(uint32_t sm_base, const __nv_bfloat16* g,
                                          int ld, int row0, int k0, int tid)
{
    #pragma unroll
    for (int i = 0; i < 2; ++i) {
        int id  = i * 256 + tid;
        int row = id >> 2;
        int ch  = id & 3;
        uint32_t sm = sm_base + row * 80 + ch * 16;
        cp16(sm, g + (size_t)(row0 + row) * ld + k0 + ch * 8);
    }
}

template<int OBF16, int HASBIAS>
__global__ void __launch_bounds__(256) gemm_mma(
    const __nv_bfloat16* __restrict__ A, const __nv_bfloat16* __restrict__ B,
    const float* __restrict__ bias, void* __restrict__ Cout,
    int N, int K, float scale, size_t sA, size_t sB, size_t sC)
{
    extern __shared__ __nv_bfloat16 smem[];
    const uint32_t sb = smem_u32(smem);
    const int tid = threadIdx.x, wid = tid >> 5, lane = tid & 31;
    const int m0 = blockIdx.y * BM, n0 = blockIdx.x * BN;
    const int z = blockIdx.z;
    A += (size_t)z * sA;
    B += (size_t)z * sB;

    const int wm = wid & 3, wn = wid >> 2;        // warp grid 4x2
    const int wrow = wm * 32, wcol = wn * 64;
    const int KT = K / BK;

    // ldmatrix byte offsets (within a stage, stage base added later)
    // A: two m16 tiles; rows wrow + mt*16 + (lane&15), k-offset (lane>>4)*8
    uint32_t a_off[2];
    #pragma unroll
    for (int mt = 0; mt < 2; ++mt)
        a_off[mt] = (wrow + mt * 16 + (lane & 15)) * 80 + ((lane >> 4) << 3) * 2;
    // B: four x4 loads covering 8 n8-tiles
    uint32_t b_off[4];
    #pragma unroll
    for (int np = 0; np < 4; ++np) {
        int n  = wcol + np * 16 + (lane & 7) + ((lane >> 4) << 3);
        int kf = ((lane >> 3) & 1) << 3;
        b_off[np] = n * 80 + kf * 2;
    }

    float acc[2][8][4];
    #pragma unroll
    for (int i = 0; i < 2; ++i)
        #pragma unroll
        for (int j = 0; j < 8; ++j)
            #pragma unroll
            for (int q = 0; q < 4; ++q) acc[i][j][q] = 0.f;

    const uint32_t sbB0 = sb + 3 * STAGE_ELEMS * 2;

    // prefetch 2 stages
    #pragma unroll
    for (int s = 0; s < 2; ++s) {
        load_tile(sb + s * STAGE_ELEMS * 2, A, K, m0, s * BK, tid);
        load_tile(sbB0 + s * STAGE_ELEMS * 2, B, K, n0, s * BK, tid);
        CP_COMMIT();
    }

    for (int it = 0; it < KT; ++it) {
        cp_wait<1>();
        __syncthreads();
        if (it + 2 < KT) {
            int s = (it + 2) % 3;
            load_tile(sb + s * STAGE_ELEMS * 2, A, K, m0, (it + 2) * BK, tid);
            load_tile(sbB0 + s * STAGE_ELEMS * 2, B, K, n0, (it + 2) * BK, tid);
        }
        CP_COMMIT();

        const uint32_t as = sb + (it % 3) * STAGE_ELEMS * 2;
        const uint32_t bs = sbB0 + (it % 3) * STAGE_ELEMS * 2;
        #pragma unroll
        for (int kk = 0; kk < 2; ++kk) {
            uint32_t a[2][4], b[8][2];
            #pragma unroll
            for (int mt = 0; mt < 2; ++mt)
                ldsm_x4(a[mt][0], a[mt][1], a[mt][2], a[mt][3], as + a_off[mt] + kk * 32);
            #pragma unroll
            for (int np = 0; np < 4; ++np)
                ldsm_x4(b[np*2][0], b[np*2][1], b[np*2+1][0], b[np*2+1][1],
                        bs + b_off[np] + kk * 32);
            #pragma unroll
            for (int mt = 0; mt < 2; ++mt)
                #pragma unroll
                for (int nt = 0; nt < 8; ++nt)
                    mma16816(acc[mt][nt], a[mt], b[nt]);
        }
    }

    // epilogue: direct global writes
    const int r_lane = lane >> 2, c_lane = (lane & 3) * 2;
    #pragma unroll
    for (int mt = 0; mt < 2; ++mt) {
        int r0 = m0 + wrow + mt * 16 + r_lane;
        #pragma unroll
        for (int nt = 0; nt < 8; ++nt) {
            int c = n0 + wcol + nt * 8 + c_lane;
            float v0 = acc[mt][nt][0] * scale, v1 = acc[mt][nt][1] * scale;
            float v2 = acc[mt][nt][2] * scale, v3 = acc[mt][nt][3] * scale;
            if (HASBIAS) {
                float b0 = bias[c], b1 = bias[c + 1];
                v0 += b0; v1 += b1; v2 += b0; v3 += b1;
            }
            if (OBF16) {
                __nv_bfloat16* Cb = (__nv_bfloat16*)Cout + (size_t)z * sC;
                *(__nv_bfloat162*)(Cb + (size_t)r0 * N + c)       = __floats2bfloat162_rn(v0, v1);
                *(__nv_bfloat162*)(Cb + (size_t)(r0 + 8) * N + c) = __floats2bfloat162_rn(v2, v3);
            } else {
                float* Cf = (float*)Cout + (size_t)z * sC;
                *(float2*)(Cf + (size_t)r0 * N + c)       = make_float2(v0, v1);
                *(float2*)(Cf + (size_t)(r0 + 8) * N + c) = make_float2(v2, v3);
            }
        }
    }
}

// ---------------- row softmax: S fp32 -> P bf16 ---------------------------------
__global__ void __launch_bounds__(256) softmax4096(const float* __restrict__ S,
                                                   __nv_bfloat16* __restrict__ P)
{
    __shared__ float redm[8], reds[8];
    const float4* p = (const float4*)(S + (size_t)blockIdx.x * HWN);
    float4 v[4];
    #pragma unroll
    for (int i = 0; i < 4; ++i) v[i] = p[threadIdx.x + 256 * i];

    float m = -3.4e38f;
    #pragma unroll
    for (int i = 0; i < 4; ++i)
        m = fmaxf(m, fmaxf(fmaxf(v[i].x, v[i].y), fmaxf(v[i].z, v[i].w)));
    #pragma unroll
    for (int o = 16; o > 0; o >>= 1) m = fmaxf(m, __shfl_xor_sync(0xffffffffu, m, o));
    int wid = threadIdx.x >> 5, lane = threadIdx.x & 31;
    if (lane == 0) redm[wid] = m;
    __syncthreads();
    if (wid == 0) {
        float t = (lane < 8) ? redm[lane] : -3.4e38f;
        #pragma unroll
        for (int o = 16; o > 0; o >>= 1) t = fmaxf(t, __shfl_xor_sync(0xffffffffu, t, o));
        if (lane == 0) redm[0] = t;
    }
    __syncthreads();
    m = redm[0];

    float s = 0.f;
    #pragma unroll
    for (int i = 0; i < 4; ++i) {
        v[i].x = __expf(v[i].x - m); v[i].y = __expf(v[i].y - m);
        v[i].z = __expf(v[i].z - m); v[i].w = __expf(v[i].w - m);
        s += v[i].x + v[i].y + v[i].z + v[i].w;
    }
    #pragma unroll
    for (int o = 16; o > 0; o >>= 1) s += __shfl_xor_sync(0xffffffffu, s, o);
    if (lane == 0) reds[wid] = s;
    __syncthreads();
    if (wid == 0) {
        float t = (lane < 8) ? reds[lane] : 0.f;
        #pragma unroll
        for (int o = 16; o > 0; o >>= 1) t += __shfl_xor_sync(0xffffffffu, t, o);
        if (lane == 0) reds[0] = t;
    }
    __syncthreads();
    float inv = 1.f / reds[0];
    __nv_bfloat162* prow = (__nv_bfloat162*)(P + (size_t)blockIdx.x * HWN);
    #pragma unroll
    for (int i = 0; i < 4; ++i) {
        prow[(threadIdx.x + 256 * i) * 2 + 0] = __floats2bfloat162_rn(v[i].x * inv, v[i].y * inv);
        prow[(threadIdx.x + 256 * i) * 2 + 1] = __floats2bfloat162_rn(v[i].z * inv, v[i].w * inv);
    }
}

// ---------------- launch ---------------------------------------------------------
extern "C" void kernel_launch(void* const* d_in, const int* in_sizes, int n_in,
                              void* d_out, int out_size)
{
    const float* x     = (const float*)d_in[0];
    const float* gamma = (const float*)d_in[1];
    const float* beta  = (const float*)d_in[2];
    const float* wq    = (const float*)d_in[3];
    const float* bq    = (const float*)d_in[4];
    const float* wk    = (const float*)d_in[5];
    const float* bk    = (const float*)d_in[6];
    const float* wv    = (const float*)d_in[7];
    const float* bv    = (const float*)d_in[8];
    const float* wp    = (const float*)d_in[9];
    const float* bp    = (const float*)d_in[10];
    float* out = (float*)d_out;

    __nv_bfloat16 *hl, *q, *k, *v, *vt, *o, *P, *wt;
    float *po, *S;
    cudaGetSymbolAddress((void**)&hl, g_hl);
    cudaGetSymbolAddress((void**)&q,  g_q);
    cudaGetSymbolAddress((void**)&k,  g_k);
    cudaGetSymbolAddress((void**)&v,  g_v);
    cudaGetSymbolAddress((void**)&vt, g_vt);
    cudaGetSymbolAddress((void**)&o,  g_o);
    cudaGetSymbolAddress((void**)&po, g_po);
    cudaGetSymbolAddress((void**)&S,  g_S);
    cudaGetSymbolAddress((void**)&P,  g_P);
    cudaGetSymbolAddress((void**)&wt, g_wt);

    cudaFuncSetAttribute(gemm_mma<0,0>, cudaFuncAttributeMaxDynamicSharedMemorySize, SMEM_GEMM);
    cudaFuncSetAttribute(gemm_mma<0,1>, cudaFuncAttributeMaxDynamicSharedMemorySize, SMEM_GEMM);
    cudaFuncSetAttribute(gemm_mma<1,0>, cudaFuncAttributeMaxDynamicSharedMemorySize, SMEM_GEMM);
    cudaFuncSetAttribute(gemm_mma<1,1>, cudaFuncAttributeMaxDynamicSharedMemorySize, SMEM_GEMM);

    dim3 tb(32, 32);

    gn_stats<<<GROUPS, 512>>>(x);
    norm_transpose<<<dim3(PN / 32, CCH / 32), tb>>>(x, gamma, beta, hl);

    __nv_bfloat16* wtq = wt + 0 * CCH * CCH;
    __nv_bfloat16* wtk = wt + 1 * CCH * CCH;
    __nv_bfloat16* wtv = wt + 2 * CCH * CCH;
    __nv_bfloat16* wtp = wt + 3 * CCH * CCH;
    wtrans<<<dim3(16, 16), tb>>>(wq, wtq);
    wtrans<<<dim3(16, 16), tb>>>(wk, wtk);
    wtrans<<<dim3(16, 16), tb>>>(wv, wtv);
    wtrans<<<dim3(16, 16), tb>>>(wp, wtp);

    // projections: M=32768, N=512, K=512
    dim3 gproj(CCH / BN, PN / BM, 1);
    gemm_mma<1,1><<<gproj, 256, SMEM_GEMM>>>(hl, wtq, bq, q, CCH, CCH, 1.f, 0, 0, 0);
    gemm_mma<1,1><<<gproj, 256, SMEM_GEMM>>>(hl, wtk, bk, k, CCH, CCH, 1.f, 0, 0, 0);
    gemm_mma<1,1><<<gproj, 256, SMEM_GEMM>>>(hl, wtv, bv, v, CCH, CCH, 1.f, 0, 0, 0);

    vtrans<<<dim3(HWN / 32, CCH / 32, TT), tb>>>(v, vt);

    const float scale = 0.044194173824159216f;  // 512^-0.5

    // scores: batched over 8 t-slices: S[t] = scale * q[t] @ k[t]^T
    gemm_mma<0,0><<<dim3(HWN / BN, HWN / BM, TT), 256, SMEM_GEMM>>>(
        q, k, nullptr, S, HWN, CCH, scale,
        (size_t)HWN * CCH, (size_t)HWN * CCH, (size_t)HWN * HWN);

    softmax4096<<<TT * HWN, 256>>>(S, P);

    // PV: batched: o[t] = P[t] @ vt[t]^T   (vt[t]: [C][HWN])
    gemm_mma<1,0><<<dim3(CCH / BN, HWN / BM, TT), 256, SMEM_GEMM>>>(
        P, vt, nullptr, o, CCH, HWN, 1.f,
        (size_t)HWN * HWN, (size_t)CCH * HWN, (size_t)HWN * CCH);

    // output projection: M=32768, N=512, K=512 (fp32 out)
    gemm_mma<0,1><<<gproj, 256, SMEM_GEMM>>>(o, wtp, bp, po, CCH, CCH, 1.f, 0, 0, 0);
    add_transpose<<<dim3(PN / 32, CCH / 32), tb>>>(x, po, out);
}

// round 4
// speedup vs baseline: 7.1126x; 1.0547x over previous
#include <cuda_runtime.h>
#include <cuda_bf16.h>
#include <math.h>
#include <stdint.h>

#define CCH   512
#define TT    8
#define HWN   4096
#define PN    (TT*HWN)
#define GROUPS 32
#define GSIZE (16*PN)

// ---------------- scratch (device globals) ----------------------------------
__device__ float g_mean[GROUPS];
__device__ float g_rstd[GROUPS];
__device__ __nv_bfloat16 g_hl[(size_t)PN * CCH];
__device__ __nv_bfloat16 g_q [(size_t)PN * CCH];
__device__ __nv_bfloat16 g_k [(size_t)PN * CCH];
__device__ __nv_bfloat16 g_v [(size_t)PN * CCH];
__device__ __nv_bfloat16 g_vt[(size_t)PN * CCH];
__device__ __nv_bfloat16 g_o [(size_t)PN * CCH];
__device__ __nv_bfloat16 g_P [(size_t)TT * HWN * HWN];   // 256 MB: scores, softmaxed in place
__device__ __nv_bfloat16 g_wt[4 * CCH * CCH];

struct Ptr3 {
    const float* b0; const float* b1; const float* b2;
    void* o0; void* o1; void* o2;
};

// ---------------- PTX helpers -------------------------------------------------
__device__ __forceinline__ uint32_t smem_u32(const void* p) {
    uint32_t a;
    asm("{ .reg .u64 t; cvta.to.shared.u64 t, %1; cvt.u32.u64 %0, t; }" : "=r"(a) : "l"(p));
    return a;
}
__device__ __forceinline__ void ldsm_x4(uint32_t& r0, uint32_t& r1, uint32_t& r2,
                                        uint32_t& r3, uint32_t addr) {
    asm volatile("ldmatrix.sync.aligned.m8n8.x4.shared.b16 {%0,%1,%2,%3}, [%4];"
                 : "=r"(r0), "=r"(r1), "=r"(r2), "=r"(r3) : "r"(addr));
}
__device__ __forceinline__ void mma16816(float* d, const uint32_t* a, const uint32_t* b) {
    asm volatile("mma.sync.aligned.m16n8k16.row.col.f32.bf16.bf16.f32 "
                 "{%0,%1,%2,%3}, {%4,%5,%6,%7}, {%8,%9}, {%0,%1,%2,%3};"
                 : "+f"(d[0]), "+f"(d[1]), "+f"(d[2]), "+f"(d[3])
                 : "r"(a[0]), "r"(a[1]), "r"(a[2]), "r"(a[3]), "r"(b[0]), "r"(b[1]));
}
__device__ __forceinline__ void cp16(uint32_t sm, const void* gp) {
    asm volatile("cp.async.cg.shared.global [%0], [%1], 16;" :: "r"(sm), "l"(gp) : "memory");
}
#define CP_COMMIT() asm volatile("cp.async.commit_group;" ::: "memory")
template<int W> __device__ __forceinline__ void cp_wait() {
    asm volatile("cp.async.wait_group %0;" :: "n"(W) : "memory");
}

// FMA-only exp (no MUFU): exp(x) = 2^(x*log2e), degree-5 poly on f in [-0.5,0.5]
__device__ __forceinline__ float fexp(float x) {
    float y = fmaxf(x * 1.44269504f, -120.f);
    float n = rintf(y);
    float f = y - n;
    float p = 0.00133336f;
    p = fmaf(p, f, 0.00961813f);
    p = fmaf(p, f, 0.05550411f);
    p = fmaf(p, f, 0.24022651f);
    p = fmaf(p, f, 0.69314718f);
    p = fmaf(p, f, 1.0f);
    return __int_as_float(__float_as_int(p) + (((int)n) << 23));
}

// ---------------- group-norm stats --------------------------------------------
__global__ void __launch_bounds__(512) gn_stats(const float* __restrict__ x) {
    int g = blockIdx.x;
    const float4* p = (const float4*)(x + (size_t)g * GSIZE);
    float s = 0.f, ss = 0.f;
    for (int i = threadIdx.x; i < GSIZE / 4; i += 512) {
        float4 v = p[i];
        s  += v.x + v.y + v.z + v.w;
        ss += v.x * v.x + v.y * v.y + v.z * v.z + v.w * v.w;
    }
    __shared__ float shs[512], shq[512];
    shs[threadIdx.x] = s; shq[threadIdx.x] = ss;
    __syncthreads();
    for (int st = 256; st > 0; st >>= 1) {
        if (threadIdx.x < st) {
            shs[threadIdx.x] += shs[threadIdx.x + st];
            shq[threadIdx.x] += shq[threadIdx.x + st];
        }
        __syncthreads();
    }
    if (threadIdx.x == 0) {
        float m = shs[0] / (float)GSIZE;
        float var = shq[0] / (float)GSIZE - m * m;
        g_mean[g] = m;
        g_rstd[g] = rsqrtf(var + 1e-6f);
    }
}

// ---------------- normalize + transpose to channels-last (bf16) ---------------
__global__ void __launch_bounds__(1024) norm_transpose(
    const float* __restrict__ x, const float* __restrict__ gamma,
    const float* __restrict__ beta, __nv_bfloat16* __restrict__ hl)
{
    __shared__ float tile[32][33];
    int p0 = blockIdx.x * 32, c0 = blockIdx.y * 32;
    int c = c0 + threadIdx.y;
    tile[threadIdx.y][threadIdx.x] = x[(size_t)c * PN + p0 + threadIdx.x];
    __syncthreads();
    int cc = c0 + threadIdx.x;
    int g = cc >> 4;
    float a = gamma[cc] * g_rstd[g];
    float b = beta[cc] - g_mean[g] * a;
    hl[(size_t)(p0 + threadIdx.y) * CCH + cc] =
        __float2bfloat16(tile[threadIdx.x][threadIdx.y] * a + b);
}

// ---------------- weight transpose fp32 [K][N] -> bf16 [N][K] ------------------
__global__ void __launch_bounds__(1024) wtrans(const float* __restrict__ W,
                                               __nv_bfloat16* __restrict__ Wt)
{
    __shared__ float t[32][33];
    int k0 = blockIdx.y * 32, n0 = blockIdx.x * 32;
    t[threadIdx.y][threadIdx.x] = W[(size_t)(k0 + threadIdx.y) * CCH + n0 + threadIdx.x];
    __syncthreads();
    Wt[(size_t)(n0 + threadIdx.y) * CCH + k0 + threadIdx.x] =
        __float2bfloat16(t[threadIdx.x][threadIdx.y]);
}

// ---------------- V transpose bf16 [t*4096+p][c] -> [t][c][p] -------------------
__global__ void __launch_bounds__(1024) vtrans(const __nv_bfloat16* __restrict__ v,
                                               __nv_bfloat16* __restrict__ vt)
{
    __shared__ __nv_bfloat16 t[32][33];
    int ts = blockIdx.z, p0 = blockIdx.x * 32, c0 = blockIdx.y * 32;
    t[threadIdx.y][threadIdx.x] =
        v[(size_t)(ts * HWN + p0 + threadIdx.y) * CCH + c0 + threadIdx.x];
    __syncthreads();
    vt[(size_t)ts * CCH * HWN + (size_t)(c0 + threadIdx.y) * HWN + p0 + threadIdx.x] =
        t[threadIdx.x][threadIdx.y];
}

// ---------------- HMMA bf16 GEMM: C = scale*(A @ B^T) [+ bias] ------------------
// A: [M][K] bf16 row-major, B: [N][K] bf16 row-major.
// CTA tile 128x128x32, 8 warps (4x2), warp tile 32x64, 3-stage cp.async pipeline.
// QKV3: z selects weight slice + bias/out from Ptr3.
// TRANSADD: epilogue does smem transpose, adds residual x, writes fp32 [C][PN].
#define BM 128
#define BN 128
#define BK 32
#define STAGE_ELEMS (BM * 40)                  // 80 B padded rows
#define SMEM_GEMM 66048                        // max(pipeline 61440, transpose 128*129*4)

__device__ __forceinline__ void load_tile(uint32_t sm_base, const __nv_bfloat16* g,
                                          int ld, int row0, int k0, int tid)
{
    #pragma unroll
    for (int i = 0; i < 2; ++i) {
        int id  = i * 256 + tid;
        int row = id >> 2;
        int ch  = id & 3;
        uint32_t sm = sm_base + row * 80 + ch * 16;
        cp16(sm, g + (size_t)(row0 + row) * ld + k0 + ch * 8);
    }
}

template<int OBF16, int HASBIAS, int QKV3, int TRANSADD>
__global__ void __launch_bounds__(256) gemm_mma(
    const __nv_bfloat16* __restrict__ A, const __nv_bfloat16* __restrict__ B,
    const float* __restrict__ bias, void* __restrict__ Cout,
    int N, int K, float scale, size_t sA, size_t sB, size_t sC,
    Ptr3 p3, const float* __restrict__ xres)
{
    extern __shared__ __nv_bfloat16 smem[];
    const uint32_t sb = smem_u32(smem);
    const int tid = threadIdx.x, wid = tid >> 5, lane = tid & 31;
    const int m0 = blockIdx.y * BM, n0 = blockIdx.x * BN;
    const int z = blockIdx.z;

    const float* bias_p = bias;
    void* outp = Cout;
    if (QKV3) {
        B += (size_t)z * (CCH * CCH);
        bias_p = (z == 0) ? p3.b0 : (z == 1) ? p3.b1 : p3.b2;
        outp   = (z == 0) ? p3.o0 : (z == 1) ? p3.o1 : p3.o2;
    } else {
        A += (size_t)z * sA;
        B += (size_t)z * sB;
    }

    const int wm = wid & 3, wn = wid >> 2;        // warp grid 4x2
    const int wrow = wm * 32, wcol = wn * 64;
    const int KT = K / BK;

    uint32_t a_off[2];
    #pragma unroll
    for (int mt = 0; mt < 2; ++mt)
        a_off[mt] = (wrow + mt * 16 + (lane & 15)) * 80 + ((lane >> 4) << 3) * 2;
    uint32_t b_off[4];
    #pragma unroll
    for (int np = 0; np < 4; ++np) {
        int n  = wcol + np * 16 + (lane & 7) + ((lane >> 4) << 3);
        int kf = ((lane >> 3) & 1) << 3;
        b_off[np] = n * 80 + kf * 2;
    }

    float acc[2][8][4];
    #pragma unroll
    for (int i = 0; i < 2; ++i)
        #pragma unroll
        for (int j = 0; j < 8; ++j)
            #pragma unroll
            for (int q = 0; q < 4; ++q) acc[i][j][q] = 0.f;

    const uint32_t sbB0 = sb + 3 * STAGE_ELEMS * 2;

    #pragma unroll
    for (int s = 0; s < 2; ++s) {
        load_tile(sb + s * STAGE_ELEMS * 2, A, K, m0, s * BK, tid);
        load_tile(sbB0 + s * STAGE_ELEMS * 2, B, K, n0, s * BK, tid);
        CP_COMMIT();
    }

    for (int it = 0; it < KT; ++it) {
        cp_wait<1>();
        __syncthreads();
        if (it + 2 < KT) {
            int s = (it + 2) % 3;
            load_tile(sb + s * STAGE_ELEMS * 2, A, K, m0, (it + 2) * BK, tid);
            load_tile(sbB0 + s * STAGE_ELEMS * 2, B, K, n0, (it + 2) * BK, tid);
        }
        CP_COMMIT();

        const uint32_t as = sb + (it % 3) * STAGE_ELEMS * 2;
        const uint32_t bs = sbB0 + (it % 3) * STAGE_ELEMS * 2;
        #pragma unroll
        for (int kk = 0; kk < 2; ++kk) {
            uint32_t a[2][4], b[8][2];
            #pragma unroll
            for (int mt = 0; mt < 2; ++mt)
                ldsm_x4(a[mt][0], a[mt][1], a[mt][2], a[mt][3], as + a_off[mt] + kk * 32);
            #pragma unroll
            for (int np = 0; np < 4; ++np)
                ldsm_x4(b[np*2][0], b[np*2][1], b[np*2+1][0], b[np*2+1][1],
                        bs + b_off[np] + kk * 32);
            #pragma unroll
            for (int mt = 0; mt < 2; ++mt)
                #pragma unroll
                for (int nt = 0; nt < 8; ++nt)
                    mma16816(acc[mt][nt], a[mt], b[nt]);
        }
    }

    const int r_lane = lane >> 2, c_lane = (lane & 3) * 2;

    if (TRANSADD) {
        // fused: bias add, transpose via smem, residual add, write fp32 [C][PN]
        __syncthreads();
        float* st = (float*)smem;
        #pragma unroll
        for (int mt = 0; mt < 2; ++mt) {
            int rl = wrow + mt * 16 + r_lane;
            #pragma unroll
            for (int nt = 0; nt < 8; ++nt) {
                int cl = wcol + nt * 8 + c_lane;
                float b0 = bias_p[n0 + cl], b1 = bias_p[n0 + cl + 1];
                st[rl * 129 + cl]           = acc[mt][nt][0] + b0;
                st[rl * 129 + cl + 1]       = acc[mt][nt][1] + b1;
                st[(rl + 8) * 129 + cl]     = acc[mt][nt][2] + b0;
                st[(rl + 8) * 129 + cl + 1] = acc[mt][nt][3] + b1;
            }
        }
        __syncthreads();
        float* of = (float*)outp;
        #pragma unroll
        for (int i = 0; i < 64; ++i) {
            int idx = i * 256 + tid;
            int ci = idx >> 7, pi = idx & 127;
            size_t gi = (size_t)(n0 + ci) * PN + (m0 + pi);
            of[gi] = xres[gi] + st[pi * 129 + ci];
        }
        return;
    }

    #pragma unroll
    for (int mt = 0; mt < 2; ++mt) {
        int r0 = m0 + wrow + mt * 16 + r_lane;
        #pragma unroll
        for (int nt = 0; nt < 8; ++nt) {
            int c = n0 + wcol + nt * 8 + c_lane;
            float v0 = acc[mt][nt][0] * scale, v1 = acc[mt][nt][1] * scale;
            float v2 = acc[mt][nt][2] * scale, v3 = acc[mt][nt][3] * scale;
            if (HASBIAS) {
                float b0 = bias_p[c], b1 = bias_p[c + 1];
                v0 += b0; v1 += b1; v2 += b0; v3 += b1;
            }
            if (OBF16) {
                __nv_bfloat16* Cb = (__nv_bfloat16*)outp + (size_t)z * sC;
                *(__nv_bfloat162*)(Cb + (size_t)r0 * N + c)       = __floats2bfloat162_rn(v0, v1);
                *(__nv_bfloat162*)(Cb + (size_t)(r0 + 8) * N + c) = __floats2bfloat162_rn(v2, v3);
            } else {
                float* Cf = (float*)outp + (size_t)z * sC;
                *(float2*)(Cf + (size_t)r0 * N + c)       = make_float2(v0, v1);
                *(float2*)(Cf + (size_t)(r0 + 8) * N + c) = make_float2(v2, v3);
            }
        }
    }
}

// ---------------- row softmax in place on bf16 rows of 4096 ---------------------
__global__ void __launch_bounds__(256) softmax_bf16(__nv_bfloat16* __restrict__ P) {
    __shared__ float redm[8], reds[8];
    uint4* row = (uint4*)(P + (size_t)blockIdx.x * HWN);
    uint4 d[2];
    float f[16];
    d[0] = row[threadIdx.x];
    d[1] = row[threadIdx.x + 256];
    #pragma unroll
    for (int j = 0; j < 2; ++j) {
        const __nv_bfloat162* h = (const __nv_bfloat162*)&d[j];
        #pragma unroll
        for (int q = 0; q < 4; ++q) {
            float2 t = __bfloat1622float2(h[q]);
            f[j * 8 + q * 2] = t.x; f[j * 8 + q * 2 + 1] = t.y;
        }
    }

    float m = -3.4e38f;
    #pragma unroll
    for (int i = 0; i < 16; ++i) m = fmaxf(m, f[i]);
    #pragma unroll
    for (int o = 16; o > 0; o >>= 1) m = fmaxf(m, __shfl_xor_sync(0xffffffffu, m, o));
    int wid = threadIdx.x >> 5, lane = threadIdx.x & 31;
    if (lane == 0) redm[wid] = m;
    __syncthreads();
    if (wid == 0) {
        float t = (lane < 8) ? redm[lane] : -3.4e38f;
        #pragma unroll
        for (int o = 16; o > 0; o >>= 1) t = fmaxf(t, __shfl_xor_sync(0xffffffffu, t, o));
        if (lane == 0) redm[0] = t;
    }
    __syncthreads();
    m = redm[0];

    float s = 0.f;
    #pragma unroll
    for (int i = 0; i < 16; ++i) { f[i] = fexp(f[i] - m); s += f[i]; }
    #pragma unroll
    for (int o = 16; o > 0; o >>= 1) s += __shfl_xor_sync(0xffffffffu, s, o);
    if (lane == 0) reds[wid] = s;
    __syncthreads();
    if (wid == 0) {
        float t = (lane < 8) ? reds[lane] : 0.f;
        #pragma unroll
        for (int o = 16; o > 0; o >>= 1) t += __shfl_xor_sync(0xffffffffu, t, o);
        if (lane == 0) reds[0] = t;
    }
    __syncthreads();
    float inv = 1.f / reds[0];

    #pragma unroll
    for (int j = 0; j < 2; ++j) {
        __nv_bfloat162* h = (__nv_bfloat162*)&d[j];
        #pragma unroll
        for (int q = 0; q < 4; ++q)
            h[q] = __floats2bfloat162_rn(f[j * 8 + q * 2] * inv, f[j * 8 + q * 2 + 1] * inv);
    }
    row[threadIdx.x]       = d[0];
    row[threadIdx.x + 256] = d[1];
}

// ---------------- launch ---------------------------------------------------------
extern "C" void kernel_launch(void* const* d_in, const int* in_sizes, int n_in,
                              void* d_out, int out_size)
{
    const float* x     = (const float*)d_in[0];
    const float* gamma = (const float*)d_in[1];
    const float* beta  = (const float*)d_in[2];
    const float* wq    = (const float*)d_in[3];
    const float* bq    = (const float*)d_in[4];
    const float* wk    = (const float*)d_in[5];
    const float* bk    = (const float*)d_in[6];
    const float* wv    = (const float*)d_in[7];
    const float* bv    = (const float*)d_in[8];
    const float* wp    = (const float*)d_in[9];
    const float* bp    = (const float*)d_in[10];
    float* out = (float*)d_out;

    __nv_bfloat16 *hl, *q, *k, *v, *vt, *o, *P, *wt;
    cudaGetSymbolAddress((void**)&hl, g_hl);
    cudaGetSymbolAddress((void**)&q,  g_q);
    cudaGetSymbolAddress((void**)&k,  g_k);
    cudaGetSymbolAddress((void**)&v,  g_v);
    cudaGetSymbolAddress((void**)&vt, g_vt);
    cudaGetSymbolAddress((void**)&o,  g_o);
    cudaGetSymbolAddress((void**)&P,  g_P);
    cudaGetSymbolAddress((void**)&wt, g_wt);

    cudaFuncSetAttribute(gemm_mma<1,1,1,0>, cudaFuncAttributeMaxDynamicSharedMemorySize, SMEM_GEMM);
    cudaFuncSetAttribute(gemm_mma<1,0,0,0>, cudaFuncAttributeMaxDynamicSharedMemorySize, SMEM_GEMM);
    cudaFuncSetAttribute(gemm_mma<0,1,0,1>, cudaFuncAttributeMaxDynamicSharedMemorySize, SMEM_GEMM);

    dim3 tb(32, 32);
    Ptr3 none = {};

    gn_stats<<<GROUPS, 512>>>(x);
    norm_transpose<<<dim3(PN / 32, CCH / 32), tb>>>(x, gamma, beta, hl);

    wtrans<<<dim3(16, 16), tb>>>(wq, wt + 0 * CCH * CCH);
    wtrans<<<dim3(16, 16), tb>>>(wk, wt + 1 * CCH * CCH);
    wtrans<<<dim3(16, 16), tb>>>(wv, wt + 2 * CCH * CCH);
    wtrans<<<dim3(16, 16), tb>>>(wp, wt + 3 * CCH * CCH);

    // fused q/k/v projections: z in {0,1,2} selects weight slice + bias + output
    Ptr3 qkv = { bq, bk, bv, q, k, v };
    gemm_mma<1,1,1,0><<<dim3(CCH / BN, PN / BM, 3), 256, SMEM_GEMM>>>(
        hl, wt, nullptr, nullptr, CCH, CCH, 1.f, 0, 0, 0, qkv, nullptr);

    vtrans<<<dim3(HWN / 32, CCH / 32, TT), tb>>>(v, vt);

    const float scale = 0.044194173824159216f;  // 512^-0.5

    // scores (bf16 out, scale fused), batched over 8 t-slices
    gemm_mma<1,0,0,0><<<dim3(HWN / BN, HWN / BM, TT), 256, SMEM_GEMM>>>(
        q, k, nullptr, P, HWN, CCH, scale,
        (size_t)HWN * CCH, (size_t)HWN * CCH, (size_t)HWN * HWN, none, nullptr);

    softmax_bf16<<<TT * HWN, 256>>>(P);

    // PV: o[t] = P[t] @ vt[t]^T
    gemm_mma<1,0,0,0><<<dim3(CCH / BN, HWN / BM, TT), 256, SMEM_GEMM>>>(
        P, vt, nullptr, o, CCH, HWN, 1.f,
        (size_t)HWN * HWN, (size_t)CCH * HWN, (size_t)HWN * CCH, none, nullptr);

    // output projection with fused transpose + residual
    gemm_mma<0,1,0,1><<<dim3(CCH / BN, PN / BM, 1), 256, SMEM_GEMM>>>(
        o, wt + 3 * CCH * CCH, bp, out, CCH, CCH, 1.f, 0, 0, 0, none, x);
}